// round 6
// baseline (speedup 1.0000x reference)
#include <cuda_runtime.h>
#include <cstdint>

// ---------------------------------------------------------------------------
// _LSTMOneMany_3289944948986 : 2-layer GRU decoder, B=512, H=2048, O=512, T=32.
// tf32 mma.sync GEMMs (tcgen05 unavailable: harness targets sm_103 family).
// Round 6: output projection folded into layer-0 input weights
// (Wfused = Wih0 @ outW), per-step out-GEMM+reduce removed, batched preds
// GEMM at the end. Pre-rounded tf32 operands, 3-stage cp.async, 2 CTAs/SM.
// ---------------------------------------------------------------------------

#define BSZ   512
#define HID   2048
#define OUTD  512
#define G3H   6144
#define GLD   12288
#define TSTEP 32

// ---- scratch (__device__ globals; no allocation allowed) ----
__device__ __align__(16) float g_g    [BSZ * GLD];    // gate pre-activations
__device__ __align__(16) float g_h0   [BSZ * HID];    // exact fp32 state
__device__ __align__(16) float g_h1   [BSZ * HID];
__device__ __align__(16) float g_h0r  [BSZ * HID];    // tf32-rounded GEMM copies
__device__ __align__(16) float g_h1r  [BSZ * HID];
__device__ __align__(16) float g_h1all[TSTEP * BSZ * HID];  // rounded h1 history
__device__ __align__(16) float g_bfus [G3H];          // fused layer-0 bias

// tf32-rounded weights / inputs
__device__ __align__(16) float w_x   [BSZ * 2 * 1024];
__device__ __align__(16) float w_emb [2048 * 1024];
__device__ __align__(16) float w_ih0 [G3H * OUTD];
__device__ __align__(16) float w_hh0 [G3H * HID];
__device__ __align__(16) float w_ih1 [G3H * HID];
__device__ __align__(16) float w_hh1 [G3H * HID];
__device__ __align__(16) float w_out [OUTD * HID];
__device__ __align__(16) float w_outT[HID * OUTD];    // outW^T (rounded)
__device__ __align__(16) float w_fus [G3H * HID];     // Wih0 @ outW (rounded)

// ---------------------------------------------------------------------------
__device__ __forceinline__ float roundtf(float x) {
    uint32_t u;
    asm("cvt.rna.tf32.f32 %0, %1;" : "=r"(u) : "f"(x));
    return __uint_as_float(u);
}

// smem tile [128 rows][32 cols] fp32; 16B-chunk XOR swizzle
__device__ __forceinline__ int swz(int row, int col) {
    return row * 32 + ((((col >> 2) ^ row) & 7) << 2) + (col & 3);
}

// ---------------------------------------------------------------------------
// GEMM: C[M,N] = A[M,K] @ B[N,K]^T, operands already tf32-rounded fp32.
// 128x128 CTA tile, 256 threads, 3-stage cp.async pipeline, 2 CTAs/SM.
// Per-N-block source select (nSplit) packs two GEMMs in one launch.
// MODE 0: raw store.
// MODE 2: embedding (bias+relu, scatter h0/h1 + rounded copies).
// MODE 4: preds epilogue — remap m=(t*512+b) -> C[b][t][n], add bias.
// MODE 5: store tf32-rounded (for Wfused).
// ---------------------------------------------------------------------------
#define STAGE_FLTS (2 * 128 * 32)            // A+B per stage (floats)
static const int SMEM_BYTES = 3 * STAGE_FLTS * 4;   // 98304

template <int MODE>
__global__ void __launch_bounds__(256, 2)
gemm_tf32(const float* __restrict__ A0, int lda0,
          const float* __restrict__ B0, int ldb0, int K0,
          const float* __restrict__ A1, int lda1,
          const float* __restrict__ B1, int ldb1, int K1,
          int nSplit,
          float* __restrict__ C, int ldc,
          const float* __restrict__ bias)
{
    extern __shared__ float smem[];   // [3][A 128x32 | B 128x32]

    const int tid = threadIdx.x;
    const int bn  = blockIdx.x;
    const int bm  = blockIdx.y;
    const int nBase = bn * 128;

    const float* A; const float* B; int lda, ldb, K;
    if (nBase < nSplit) {
        A = A0; lda = lda0; B = B0 + (size_t)nBase * ldb0; ldb = ldb0; K = K0;
    } else {
        A = A1; lda = lda1; B = B1 + (size_t)(nBase - nSplit) * ldb1; ldb = ldb1; K = K1;
    }
    A += (size_t)bm * 128 * lda;

    const int tRow   = tid >> 3;   // 0..31
    const int tChunk = tid & 7;    // 0..7

    const int lane = tid & 31;
    const int warp = tid >> 5;
    const int wm = (warp >> 2) << 6;   // 0 / 64
    const int wn = (warp & 3) << 5;    // 0,32,64,96
    const int lr = lane >> 2;          // 0..7
    const int lc = lane & 3;           // 0..3

    float acc[4][4][4];
#pragma unroll
    for (int i = 0; i < 4; i++)
#pragma unroll
        for (int j = 0; j < 4; j++)
#pragma unroll
            for (int k = 0; k < 4; k++) acc[i][j][k] = 0.f;

    auto load_stage = [&](int buf, int k0) {
        float* sA = smem + buf * STAGE_FLTS;
        float* sB = sA + 128 * 32;
#pragma unroll
        for (int p = 0; p < 4; p++) {
            int row = tRow + p * 32;
            int dst = row * 32 + (((tChunk ^ row) & 7) << 2);
            const float* srcA = A + (size_t)row * lda + k0 + tChunk * 4;
            const float* srcB = B + (size_t)row * ldb + k0 + tChunk * 4;
            uint32_t da = (uint32_t)__cvta_generic_to_shared(&sA[dst]);
            uint32_t db = (uint32_t)__cvta_generic_to_shared(&sB[dst]);
            asm volatile("cp.async.cg.shared.global [%0], [%1], 16;\n" :: "r"(da), "l"(srcA));
            asm volatile("cp.async.cg.shared.global [%0], [%1], 16;\n" :: "r"(db), "l"(srcB));
        }
        asm volatile("cp.async.commit_group;\n");
    };

    const int nStages = K >> 5;        // K multiple of 64 everywhere -> >= 2
    load_stage(0, 0);
    if (nStages > 1) load_stage(1, 32);
    int buf = 0;

    for (int st = 0; st < nStages; st++) {
        if (st + 2 < nStages) {
            load_stage((st + 2) % 3, (st + 2) * 32);
            asm volatile("cp.async.wait_group 2;\n");
        } else if (st + 1 < nStages) {
            asm volatile("cp.async.wait_group 1;\n");
        } else {
            asm volatile("cp.async.wait_group 0;\n");
        }
        __syncthreads();

        const uint32_t* cA = (const uint32_t*)(smem + buf * STAGE_FLTS);
        const uint32_t* cB = cA + 128 * 32;

#pragma unroll
        for (int kk = 0; kk < 4; kk++) {
            const int k8 = kk * 8;
            uint32_t af[4][4], bf[4][2];
#pragma unroll
            for (int mt = 0; mt < 4; mt++) {
                int r = wm + mt * 16 + lr;
                af[mt][0] = cA[swz(r,     k8 + lc)];
                af[mt][1] = cA[swz(r + 8, k8 + lc)];
                af[mt][2] = cA[swz(r,     k8 + lc + 4)];
                af[mt][3] = cA[swz(r + 8, k8 + lc + 4)];
            }
#pragma unroll
            for (int nt = 0; nt < 4; nt++) {
                int r = wn + nt * 8 + lr;
                bf[nt][0] = cB[swz(r, k8 + lc)];
                bf[nt][1] = cB[swz(r, k8 + lc + 4)];
            }
#pragma unroll
            for (int mt = 0; mt < 4; mt++)
#pragma unroll
                for (int nt = 0; nt < 4; nt++) {
                    float* c = acc[mt][nt];
                    asm volatile(
                        "mma.sync.aligned.m16n8k8.row.col.f32.tf32.tf32.f32 "
                        "{%0,%1,%2,%3}, {%4,%5,%6,%7}, {%8,%9}, {%0,%1,%2,%3};\n"
                        : "+f"(c[0]), "+f"(c[1]), "+f"(c[2]), "+f"(c[3])
                        : "r"(af[mt][0]), "r"(af[mt][1]), "r"(af[mt][2]), "r"(af[mt][3]),
                          "r"(bf[nt][0]), "r"(bf[nt][1]));
                }
        }
        __syncthreads();
        buf = (buf + 1) % 3;
    }

    // -------- epilogue --------
#pragma unroll
    for (int mt = 0; mt < 4; mt++)
#pragma unroll
        for (int nt = 0; nt < 4; nt++) {
            int m = bm * 128 + wm + mt * 16 + lr;
            int n = nBase + wn + nt * 8 + lc * 2;
            float2 v0 = make_float2(acc[mt][nt][0], acc[mt][nt][1]);
            float2 v1 = make_float2(acc[mt][nt][2], acc[mt][nt][3]);
            if (MODE == 0) {
                *(float2*)&C[(size_t)m       * ldc + n] = v0;
                *(float2*)&C[(size_t)(m + 8) * ldc + n] = v1;
            } else if (MODE == 5) {
                *(float2*)&C[(size_t)m       * ldc + n] =
                    make_float2(roundtf(v0.x), roundtf(v0.y));
                *(float2*)&C[(size_t)(m + 8) * ldc + n] =
                    make_float2(roundtf(v1.x), roundtf(v1.y));
            } else if (MODE == 4) {
                // m = t*512 + b; preds index = b*(32*512) + t*512 + n
                float b0 = bias[n], b1 = bias[n + 1];
                v0.x += b0; v0.y += b1; v1.x += b0; v1.y += b1;
                int b_0 = m & 511,       t_0 = m >> 9;
                int b_1 = (m + 8) & 511, t_1 = (m + 8) >> 9;
                *(float2*)&C[((size_t)b_0 << 14) + (t_0 << 9) + n] = v0;
                *(float2*)&C[((size_t)b_1 << 14) + (t_1 << 9) + n] = v1;
            } else {  // MODE 2: embedding -> relu; scatter to h0/h1 (+ rounded)
                float b0 = bias[n], b1 = bias[n + 1];
                v0.x = fmaxf(v0.x + b0, 0.f); v0.y = fmaxf(v0.y + b1, 0.f);
                v1.x = fmaxf(v1.x + b0, 0.f); v1.y = fmaxf(v1.y + b1, 0.f);
                float* hp = (m & 1) ? g_h1  : g_h0;
                float* hr = (m & 1) ? g_h1r : g_h0r;
                size_t o0 = (size_t)(m >> 1) * HID + n;
                size_t o1 = o0 + 4 * HID;              // rows m, m+8 same parity
                *(float2*)&hp[o0] = v0;
                *(float2*)&hp[o1] = v1;
                *(float2*)&hr[o0] = make_float2(roundtf(v0.x), roundtf(v0.y));
                *(float2*)&hr[o1] = make_float2(roundtf(v1.x), roundtf(v1.y));
            }
        }
}

// ---------------------------------------------------------------------------
// GRU gates. Writes exact fp32 h + tf32-rounded copy (+ optional history).
// ---------------------------------------------------------------------------
__global__ void __launch_bounds__(256)
gru_gates(const float* __restrict__ g,
          const float* __restrict__ bih, const float* __restrict__ bhh,
          float* __restrict__ h, float* __restrict__ hr,
          float* __restrict__ hstore, int hasGx)
{
    int idx = blockIdx.x * 256 + threadIdx.x;   // < 512*2048
    int b = idx >> 11, j = idx & 2047;
    const float* gb = g + (size_t)b * GLD;

    float gxr = bih[j], gxz = bih[HID + j], gxn = bih[2 * HID + j];
    if (hasGx) { gxr += gb[j]; gxz += gb[HID + j]; gxn += gb[2 * HID + j]; }
    float ghr = gb[G3H + j]           + bhh[j];
    float ghz = gb[G3H + HID + j]     + bhh[HID + j];
    float ghn = gb[G3H + 2 * HID + j] + bhh[2 * HID + j];

    float r = 1.f / (1.f + expf(-(gxr + ghr)));
    float z = 1.f / (1.f + expf(-(gxz + ghz)));
    float n = tanhf(gxn + r * ghn);
    float hn = (1.f - z) * n + z * h[idx];
    h[idx]  = hn;
    float hnr = roundtf(hn);
    hr[idx] = hnr;
    if (hstore) hstore[idx] = hnr;
}

// ---------------------------------------------------------------------------
// One-launch fp32 -> tf32 conversion of all weights/inputs (7 segments).
// ---------------------------------------------------------------------------
__global__ void __launch_bounds__(256)
convAll(const float* s0, float* d0, int n0, const float* s1, float* d1, int n1,
        const float* s2, float* d2, int n2, const float* s3, float* d3, int n3,
        const float* s4, float* d4, int n4, const float* s5, float* d5, int n5,
        const float* s6, float* d6, int n6)
{
    int i = blockIdx.x * 256 + threadIdx.x;
    if      (i < n0)                          d0[i] = roundtf(s0[i]);
    else if ((i -= n0) < n1)                  d1[i] = roundtf(s1[i]);
    else if ((i -= n1) < n2)                  d2[i] = roundtf(s2[i]);
    else if ((i -= n2) < n3)                  d3[i] = roundtf(s3[i]);
    else if ((i -= n3) < n4)                  d4[i] = roundtf(s4[i]);
    else if ((i -= n4) < n5)                  d5[i] = roundtf(s5[i]);
    else if ((i -= n5) < n6)                  d6[i] = roundtf(s6[i]);
}

// outW [512][2048] -> w_outT [2048][512], tf32-rounded.
__global__ void __launch_bounds__(256)
transpose_round(const float* __restrict__ src, float* __restrict__ dst)
{
    __shared__ float tile[32][33];
    int hx = blockIdx.x * 32, oy = blockIdx.y * 32;
    int tx = threadIdx.x & 31, ty = threadIdx.x >> 5;   // 32 x 8
#pragma unroll
    for (int p = 0; p < 4; p++)
        tile[ty + p * 8][tx] = src[(size_t)(oy + ty + p * 8) * HID + hx + tx];
    __syncthreads();
#pragma unroll
    for (int p = 0; p < 4; p++)
        dst[(size_t)(hx + ty + p * 8) * OUTD + oy + tx] =
            roundtf(tile[tx][ty + p * 8]);
}

// bfused[j] = bih0[j] + sum_o Wih0[j][o] * outB[o]   (exact fp32)
__global__ void __launch_bounds__(128)
bfused_kernel(const float* __restrict__ Wih0, const float* __restrict__ outB,
              const float* __restrict__ bih0, float* __restrict__ bfus)
{
    __shared__ float red[128];
    int j = blockIdx.x;
    float s = 0.f;
    for (int o = threadIdx.x; o < OUTD; o += 128)
        s += Wih0[(size_t)j * OUTD + o] * outB[o];
    red[threadIdx.x] = s;
    __syncthreads();
    for (int w = 64; w > 0; w >>= 1) {
        if (threadIdx.x < w) red[threadIdx.x] += red[threadIdx.x + w];
        __syncthreads();
    }
    if (threadIdx.x == 0) bfus[j] = red[0] + bih0[j];
}

// ---------------------------------------------------------------------------

extern "C" void kernel_launch(void* const* d_in, const int* in_sizes, int n_in,
                              void* d_out, int out_size)
{
    const float* x    = (const float*)d_in[0];
    const float* embB = (const float*)d_in[2];
    const float* Wih0 = (const float*)d_in[3];
    const float* bih0 = (const float*)d_in[5];
    const float* bhh0 = (const float*)d_in[6];
    const float* bih1 = (const float*)d_in[9];
    const float* bhh1 = (const float*)d_in[10];
    const float* outW = (const float*)d_in[11];
    const float* outB = (const float*)d_in[12];
    float* out = (float*)d_out;                  // [512, 32, 512]

    cudaFuncSetAttribute(gemm_tf32<0>,
                         cudaFuncAttributeMaxDynamicSharedMemorySize, SMEM_BYTES);
    cudaFuncSetAttribute(gemm_tf32<2>,
                         cudaFuncAttributeMaxDynamicSharedMemorySize, SMEM_BYTES);
    cudaFuncSetAttribute(gemm_tf32<4>,
                         cudaFuncAttributeMaxDynamicSharedMemorySize, SMEM_BYTES);
    cudaFuncSetAttribute(gemm_tf32<5>,
                         cudaFuncAttributeMaxDynamicSharedMemorySize, SMEM_BYTES);

    void* p;
    cudaGetSymbolAddress(&p, g_g);     float* g     = (float*)p;
    cudaGetSymbolAddress(&p, g_h0);    float* h0    = (float*)p;
    cudaGetSymbolAddress(&p, g_h1);    float* h1    = (float*)p;
    cudaGetSymbolAddress(&p, g_h0r);   float* h0r   = (float*)p;
    cudaGetSymbolAddress(&p, g_h1r);   float* h1r   = (float*)p;
    cudaGetSymbolAddress(&p, g_h1all); float* h1all = (float*)p;
    cudaGetSymbolAddress(&p, g_bfus);  float* bfus  = (float*)p;
    cudaGetSymbolAddress(&p, w_x);     float* xr    = (float*)p;
    cudaGetSymbolAddress(&p, w_emb);   float* eW    = (float*)p;
    cudaGetSymbolAddress(&p, w_ih0);   float* i0    = (float*)p;
    cudaGetSymbolAddress(&p, w_hh0);   float* r0    = (float*)p;
    cudaGetSymbolAddress(&p, w_ih1);   float* i1    = (float*)p;
    cudaGetSymbolAddress(&p, w_hh1);   float* r1    = (float*)p;
    cudaGetSymbolAddress(&p, w_out);   float* oW    = (float*)p;
    cudaGetSymbolAddress(&p, w_outT);  float* oWT   = (float*)p;
    cudaGetSymbolAddress(&p, w_fus);   float* fus   = (float*)p;

    const int BIG = 1 << 30;
    const dim3 gGates(BSZ * HID / 256);

    // [0] all fp32->tf32 conversions in one launch
    {
        const int n0 = BSZ * 2 * 1024, n1 = 2048 * 1024, n2 = G3H * OUTD;
        const int n3 = G3H * HID, n4 = G3H * HID, n5 = G3H * HID;
        const int n6 = OUTD * HID;
        int total = n0 + n1 + n2 + n3 + n4 + n5 + n6;
        convAll<<<(total + 255) / 256, 256>>>(
            x, xr, n0, (const float*)d_in[1], eW, n1,
            Wih0, i0, n2, (const float*)d_in[4], r0, n3,
            (const float*)d_in[7], i1, n4, (const float*)d_in[8], r1, n5,
            outW, oW, n6);
    }
    // [1] outW^T (rounded) for the Wfused GEMM
    transpose_round<<<dim3(HID / 32, OUTD / 32), 256>>>(outW, oWT);

    // [2] Wfused = Wih0 @ outW : M=6144, N=2048, K=512, rounded store
    gemm_tf32<5><<<dim3(HID / 128, G3H / 128), 256, SMEM_BYTES>>>(
        i0, OUTD, oWT, OUTD, OUTD,
        i0, OUTD, oWT, OUTD, OUTD,
        BIG, fus, HID, nullptr);

    // [3] bfused = Wih0 @ outB + bih0 (exact fp32)
    bfused_kernel<<<G3H, 128>>>(Wih0, outB, bih0, bfus);

    // [4] Embedding: M=1024 (b*2+l), N=2048, K=1024 -> relu -> h0/h1 + rounded
    gemm_tf32<2><<<dim3(2048 / 128, 1024 / 128), 256, SMEM_BYTES>>>(
        xr, 1024, eW, 1024, 1024,
        xr, 1024, eW, 1024, 1024,
        BIG, nullptr, 0, embB);

    // [5..] 2 warmup steps (zero input: gx0 skipped, gates use bias only)
    for (int w = 0; w < 2; w++) {
        gemm_tf32<0><<<dim3(G3H / 128, BSZ / 128), 256, SMEM_BYTES>>>(   // gh0
            h0r, HID, r0, HID, HID,
            h0r, HID, r0, HID, HID,
            BIG, g + G3H, GLD, nullptr);
        gru_gates<<<gGates, 256>>>(g, bih0, bhh0, h0, h0r, nullptr, 0);

        gemm_tf32<0><<<dim3(GLD / 128, BSZ / 128), 256, SMEM_BYTES>>>(   // gx1|gh1
            h0r, HID, i1, HID, HID,
            h1r, HID, r1, HID, HID,
            G3H, g, GLD, nullptr);
        // after second warmup, h1 is the state that produces preds[:,0,:]
        gru_gates<<<gGates, 256>>>(g, bih1, bhh1, h1, h1r,
                                   (w == 1) ? h1all : nullptr, 1);
    }

    // Feedback steps t = 1..31 (out-projection folded into Wfused)
    for (int t = 1; t < TSTEP; t++) {
        gemm_tf32<0><<<dim3(GLD / 128, BSZ / 128), 256, SMEM_BYTES>>>(   // gx0|gh0
            h1r, HID, fus, HID, HID,
            h0r, HID, r0,  HID, HID,
            G3H, g, GLD, nullptr);
        gru_gates<<<gGates, 256>>>(g, bfus, bhh0, h0, h0r, nullptr, 1);

        gemm_tf32<0><<<dim3(GLD / 128, BSZ / 128), 256, SMEM_BYTES>>>(   // gx1|gh1
            h0r, HID, i1, HID, HID,
            h1r, HID, r1, HID, HID,
            G3H, g, GLD, nullptr);
        gru_gates<<<gGates, 256>>>(g, bih1, bhh1, h1, h1r,
                                   h1all + (size_t)t * BSZ * HID, 1);
    }

    // Batched preds: [32*512, 512] = h1all[16384, 2048] @ outW^T + outB,
    // epilogue remaps rows (t,b) -> preds[b][t][:].
    gemm_tf32<4><<<dim3(OUTD / 128, (TSTEP * BSZ) / 128), 256, SMEM_BYTES>>>(
        h1all, HID, oW, HID, HID,
        h1all, HID, oW, HID, HID,
        BIG, out, 0, outB);
}

// round 7
// speedup vs baseline: 1.0001x; 1.0001x over previous
#include <cuda_runtime.h>
#include <cstdint>

// ---------------------------------------------------------------------------
// _LSTMOneMany_3289944948986 : 2-layer GRU decoder, B=512, H=2048, O=512, T=32.
// tf32 mma.sync GEMMs (tcgen05 unavailable: harness targets sm_103 family).
// Round 7: revert R6 fusion (FLOP-negative). R5 structure + padded-stride-36
// smem (conflict-free, zero swizzle ALU, all-immediate LDS offsets), float4
// gates/reduce, conv in 2 launches (launch #5 = main GEMM for ncu -s 5).
// ---------------------------------------------------------------------------

#define BSZ   512
#define HID   2048
#define OUTD  512
#define G3H   6144
#define GLD   12288
#define KSPLIT 8
#define PAD   36                     // padded floats per 32-col tile row

// ---- scratch (__device__ globals; no allocation allowed) ----
__device__ __align__(16) float g_g   [BSZ * GLD];     // gate pre-activations
__device__ __align__(16) float g_h0  [BSZ * HID];     // exact fp32 state
__device__ __align__(16) float g_h1  [BSZ * HID];
__device__ __align__(16) float g_h0r [BSZ * HID];     // tf32-rounded GEMM copies
__device__ __align__(16) float g_h1r [BSZ * HID];
__device__ __align__(16) float g_outr[BSZ * OUTD];    // rounded feedback input
__device__ __align__(16) float g_part[KSPLIT * BSZ * OUTD];

// tf32-rounded weights / inputs
__device__ __align__(16) float w_x   [BSZ * 2 * 1024];
__device__ __align__(16) float w_emb [2048 * 1024];
__device__ __align__(16) float w_ih0 [G3H * OUTD];
__device__ __align__(16) float w_hh0 [G3H * HID];
__device__ __align__(16) float w_ih1 [G3H * HID];
__device__ __align__(16) float w_hh1 [G3H * HID];
__device__ __align__(16) float w_out [OUTD * HID];

// ---------------------------------------------------------------------------
__device__ __forceinline__ float roundtf(float x) {
    uint32_t u;
    asm("cvt.rna.tf32.f32 %0, %1;" : "=r"(u) : "f"(x));
    return __uint_as_float(u);
}

// ---------------------------------------------------------------------------
// GEMM: C[M,N] = A[M,K] @ B[N,K]^T, operands already tf32-rounded fp32.
// 128x128 CTA tile, 256 threads, 3-stage cp.async pipeline, 2 CTAs/SM.
// Smem tiles are [128 rows][32 cols] at 36-float row stride:
//   bank(word) = (36r + c) & 31 = (4r + c) & 31  -> the warp's 8 rows x 4 cols
//   hit 32 distinct banks with NO swizzle; all frag loads are [base + imm].
// Per-N-block source select (nSplit) packs two GEMMs in one launch.
// MODE 0: raw store.  MODE 2: embedding (bias+relu, scatter h0/h1 + rounded).
// MODE 3: split-K partial (blockIdx.z slice of K) into g_part.
// ---------------------------------------------------------------------------
#define STAGE_FLTS (2 * 128 * PAD)                 // A+B per stage = 9216 floats
static const int SMEM_BYTES = 3 * STAGE_FLTS * 4;  // 110592

template <int MODE>
__global__ void __launch_bounds__(256, 2)
gemm_tf32(const float* __restrict__ A0, int lda0,
          const float* __restrict__ B0, int ldb0, int K0,
          const float* __restrict__ A1, int lda1,
          const float* __restrict__ B1, int ldb1, int K1,
          int nSplit,
          float* __restrict__ C, int ldc,
          const float* __restrict__ bias)
{
    extern __shared__ float smem[];   // [3][A 128x36 | B 128x36]

    const int tid = threadIdx.x;
    const int bn  = blockIdx.x;
    const int bm  = blockIdx.y;
    const int nBase = bn * 128;

    const float* A; const float* B; int lda, ldb, K;
    if (nBase < nSplit) {
        A = A0; lda = lda0; B = B0 + (size_t)nBase * ldb0; ldb = ldb0; K = K0;
    } else {
        A = A1; lda = lda1; B = B1 + (size_t)(nBase - nSplit) * ldb1; ldb = ldb1; K = K1;
    }
    A += (size_t)bm * 128 * lda;
    if (MODE == 3) {
        int koff = blockIdx.z * K;
        A += koff; B += koff;
        C += (size_t)blockIdx.z * (BSZ * OUTD);
    }

    const int tRow   = tid >> 3;   // 0..31
    const int tChunk = tid & 7;    // 0..7

    const int lane = tid & 31;
    const int warp = tid >> 5;
    const int wm = (warp >> 2) << 6;   // 0 / 64
    const int wn = (warp & 3) << 5;    // 0,32,64,96
    const int lr = lane >> 2;          // 0..7
    const int lc = lane & 3;           // 0..3

    // per-thread fragment base offsets (floats) within a stage
    const int aBase = (wm + lr) * PAD + lc;
    const int bBase = 128 * PAD + (wn + lr) * PAD + lc;

    float acc[4][4][4];
#pragma unroll
    for (int i = 0; i < 4; i++)
#pragma unroll
        for (int j = 0; j < 4; j++)
#pragma unroll
            for (int k = 0; k < 4; k++) acc[i][j][k] = 0.f;

    auto load_stage = [&](int buf, int k0) {
        float* sA = smem + buf * STAGE_FLTS;
        float* sB = sA + 128 * PAD;
#pragma unroll
        for (int p = 0; p < 4; p++) {
            int row = tRow + p * 32;
            int dst = row * PAD + tChunk * 4;
            const float* srcA = A + (size_t)row * lda + k0 + tChunk * 4;
            const float* srcB = B + (size_t)row * ldb + k0 + tChunk * 4;
            uint32_t da = (uint32_t)__cvta_generic_to_shared(&sA[dst]);
            uint32_t db = (uint32_t)__cvta_generic_to_shared(&sB[dst]);
            asm volatile("cp.async.cg.shared.global [%0], [%1], 16;\n" :: "r"(da), "l"(srcA));
            asm volatile("cp.async.cg.shared.global [%0], [%1], 16;\n" :: "r"(db), "l"(srcB));
        }
        asm volatile("cp.async.commit_group;\n");
    };

    const int nStages = K >> 5;        // K multiple of 64 everywhere -> >= 2
    load_stage(0, 0);
    if (nStages > 1) load_stage(1, 32);
    int buf = 0;

    for (int st = 0; st < nStages; st++) {
        if (st + 2 < nStages) {
            load_stage((st + 2) % 3, (st + 2) * 32);
            asm volatile("cp.async.wait_group 2;\n");
        } else if (st + 1 < nStages) {
            asm volatile("cp.async.wait_group 1;\n");
        } else {
            asm volatile("cp.async.wait_group 0;\n");
        }
        __syncthreads();

        const uint32_t* cA = (const uint32_t*)(smem + buf * STAGE_FLTS) + aBase;
        const uint32_t* cB = (const uint32_t*)(smem + buf * STAGE_FLTS) + bBase;

#pragma unroll
        for (int kk = 0; kk < 4; kk++) {
            const int k8 = kk * 8;     // immediate
            uint32_t af[4][4], bf[4][2];
#pragma unroll
            for (int mt = 0; mt < 4; mt++) {
                af[mt][0] = cA[mt * 16 * PAD + k8];            // (r,     lc)
                af[mt][1] = cA[mt * 16 * PAD + 8 * PAD + k8];  // (r + 8, lc)
                af[mt][2] = cA[mt * 16 * PAD + k8 + 4];        // (r,     lc+4)
                af[mt][3] = cA[mt * 16 * PAD + 8 * PAD + k8 + 4];
            }
#pragma unroll
            for (int nt = 0; nt < 4; nt++) {
                bf[nt][0] = cB[nt * 8 * PAD + k8];
                bf[nt][1] = cB[nt * 8 * PAD + k8 + 4];
            }
#pragma unroll
            for (int mt = 0; mt < 4; mt++)
#pragma unroll
                for (int nt = 0; nt < 4; nt++) {
                    float* c = acc[mt][nt];
                    asm volatile(
                        "mma.sync.aligned.m16n8k8.row.col.f32.tf32.tf32.f32 "
                        "{%0,%1,%2,%3}, {%4,%5,%6,%7}, {%8,%9}, {%0,%1,%2,%3};\n"
                        : "+f"(c[0]), "+f"(c[1]), "+f"(c[2]), "+f"(c[3])
                        : "r"(af[mt][0]), "r"(af[mt][1]), "r"(af[mt][2]), "r"(af[mt][3]),
                          "r"(bf[nt][0]), "r"(bf[nt][1]));
                }
        }
        __syncthreads();
        buf = (buf + 1) % 3;
    }

    // -------- epilogue --------
#pragma unroll
    for (int mt = 0; mt < 4; mt++)
#pragma unroll
        for (int nt = 0; nt < 4; nt++) {
            int m = bm * 128 + wm + mt * 16 + lr;
            int n = nBase + wn + nt * 8 + lc * 2;
            float2 v0 = make_float2(acc[mt][nt][0], acc[mt][nt][1]);
            float2 v1 = make_float2(acc[mt][nt][2], acc[mt][nt][3]);
            if (MODE == 0 || MODE == 3) {
                *(float2*)&C[(size_t)m       * ldc + n] = v0;
                *(float2*)&C[(size_t)(m + 8) * ldc + n] = v1;
            } else {  // MODE 2: embedding -> relu; scatter to h0/h1 (+ rounded)
                float b0 = bias[n], b1 = bias[n + 1];
                v0.x = fmaxf(v0.x + b0, 0.f); v0.y = fmaxf(v0.y + b1, 0.f);
                v1.x = fmaxf(v1.x + b0, 0.f); v1.y = fmaxf(v1.y + b1, 0.f);
                float* hp = (m & 1) ? g_h1  : g_h0;
                float* hr = (m & 1) ? g_h1r : g_h0r;
                size_t o0 = (size_t)(m >> 1) * HID + n;
                size_t o1 = o0 + 4 * HID;              // rows m, m+8 same parity
                *(float2*)&hp[o0] = v0;
                *(float2*)&hp[o1] = v1;
                *(float2*)&hr[o0] = make_float2(roundtf(v0.x), roundtf(v0.y));
                *(float2*)&hr[o1] = make_float2(roundtf(v1.x), roundtf(v1.y));
            }
        }
}

// ---------------------------------------------------------------------------
// GRU gates (float4): r=sig(gx_r+gh_r), z=sig(gx_z+gh_z), n=tanh(gx_n+r*gh_n),
//                     h = (1-z)*n + z*h.  Writes exact fp32 h + rounded copy.
// ---------------------------------------------------------------------------
__global__ void __launch_bounds__(256)
gru_gates(const float* __restrict__ g,
          const float* __restrict__ bih, const float* __restrict__ bhh,
          float* __restrict__ h, float* __restrict__ hr, int hasGx)
{
    int idx = (blockIdx.x * 256 + threadIdx.x) * 4;   // < 512*2048
    int b = idx >> 11, j = idx & 2047;
    const float* gb = g + (size_t)b * GLD;

    float4 gxr = *(const float4*)&bih[j];
    float4 gxz = *(const float4*)&bih[HID + j];
    float4 gxn = *(const float4*)&bih[2 * HID + j];
    if (hasGx) {
        float4 a = *(const float4*)&gb[j];
        float4 c = *(const float4*)&gb[HID + j];
        float4 d = *(const float4*)&gb[2 * HID + j];
        gxr.x += a.x; gxr.y += a.y; gxr.z += a.z; gxr.w += a.w;
        gxz.x += c.x; gxz.y += c.y; gxz.z += c.z; gxz.w += c.w;
        gxn.x += d.x; gxn.y += d.y; gxn.z += d.z; gxn.w += d.w;
    }
    float4 ghr = *(const float4*)&gb[G3H + j];
    float4 ghz = *(const float4*)&gb[G3H + HID + j];
    float4 ghn = *(const float4*)&gb[G3H + 2 * HID + j];
    float4 br  = *(const float4*)&bhh[j];
    float4 bz  = *(const float4*)&bhh[HID + j];
    float4 bn  = *(const float4*)&bhh[2 * HID + j];
    float4 hp  = *(const float4*)&h[idx];

    float4 ho, hro;
#pragma unroll
    for (int q = 0; q < 4; q++) {
        float xr = ((float*)&gxr)[q], xz = ((float*)&gxz)[q], xn = ((float*)&gxn)[q];
        float vr = ((float*)&ghr)[q] + ((float*)&br)[q];
        float vz = ((float*)&ghz)[q] + ((float*)&bz)[q];
        float vn = ((float*)&ghn)[q] + ((float*)&bn)[q];
        float r = 1.f / (1.f + expf(-(xr + vr)));
        float z = 1.f / (1.f + expf(-(xz + vz)));
        float n = tanhf(xn + r * vn);
        float hv = (1.f - z) * n + z * ((float*)&hp)[q];
        ((float*)&ho)[q]  = hv;
        ((float*)&hro)[q] = roundtf(hv);
    }
    *(float4*)&h[idx]  = ho;
    *(float4*)&hr[idx] = hro;
}

// Reduce split-K partials + bias -> exact preds slice + rounded feedback buf.
__global__ void __launch_bounds__(256)
out_reduce(const float* __restrict__ outB, float* __restrict__ preds)
{
    int idx = (blockIdx.x * 256 + threadIdx.x) * 4;   // < 512*512
    int o = idx & 511, b = idx >> 9;
    float4 v = *(const float4*)&outB[o];
#pragma unroll
    for (int z = 0; z < KSPLIT; z++) {
        float4 pz = *(const float4*)&g_part[z * (BSZ * OUTD) + idx];
        v.x += pz.x; v.y += pz.y; v.z += pz.z; v.w += pz.w;
    }
    *(float4*)&preds[(size_t)b * (32 * OUTD) + o] = v;
    *(float4*)&g_outr[idx] =
        make_float4(roundtf(v.x), roundtf(v.y), roundtf(v.z), roundtf(v.w));
}

// fp32 -> tf32-rounded fp32, 4 segments per launch
__global__ void __launch_bounds__(256)
conv4(const float* s0, float* d0, int n0, const float* s1, float* d1, int n1,
      const float* s2, float* d2, int n2, const float* s3, float* d3, int n3)
{
    int i = blockIdx.x * 256 + threadIdx.x;
    if      (i < n0)         d0[i] = roundtf(s0[i]);
    else if ((i -= n0) < n1) d1[i] = roundtf(s1[i]);
    else if ((i -= n1) < n2) d2[i] = roundtf(s2[i]);
    else if ((i -= n2) < n3) d3[i] = roundtf(s3[i]);
}

// ---------------------------------------------------------------------------

extern "C" void kernel_launch(void* const* d_in, const int* in_sizes, int n_in,
                              void* d_out, int out_size)
{
    const float* x    = (const float*)d_in[0];
    const float* embB = (const float*)d_in[2];
    const float* bih0 = (const float*)d_in[5];
    const float* bhh0 = (const float*)d_in[6];
    const float* bih1 = (const float*)d_in[9];
    const float* bhh1 = (const float*)d_in[10];
    const float* outB = (const float*)d_in[12];
    float* out = (float*)d_out;                  // [512, 32, 512]

    cudaFuncSetAttribute(gemm_tf32<0>,
                         cudaFuncAttributeMaxDynamicSharedMemorySize, SMEM_BYTES);
    cudaFuncSetAttribute(gemm_tf32<2>,
                         cudaFuncAttributeMaxDynamicSharedMemorySize, SMEM_BYTES);
    cudaFuncSetAttribute(gemm_tf32<3>,
                         cudaFuncAttributeMaxDynamicSharedMemorySize, SMEM_BYTES);

    void* p;
    cudaGetSymbolAddress(&p, g_g);    float* g    = (float*)p;
    cudaGetSymbolAddress(&p, g_h0);   float* h0   = (float*)p;
    cudaGetSymbolAddress(&p, g_h1);   float* h1   = (float*)p;
    cudaGetSymbolAddress(&p, g_h0r);  float* h0r  = (float*)p;
    cudaGetSymbolAddress(&p, g_h1r);  float* h1r  = (float*)p;
    cudaGetSymbolAddress(&p, g_outr); float* outr = (float*)p;
    cudaGetSymbolAddress(&p, g_part); float* part = (float*)p;
    cudaGetSymbolAddress(&p, w_x);    float* xr   = (float*)p;
    cudaGetSymbolAddress(&p, w_emb);  float* eW   = (float*)p;
    cudaGetSymbolAddress(&p, w_ih0);  float* i0   = (float*)p;
    cudaGetSymbolAddress(&p, w_hh0);  float* r0   = (float*)p;
    cudaGetSymbolAddress(&p, w_ih1);  float* i1   = (float*)p;
    cudaGetSymbolAddress(&p, w_hh1);  float* r1   = (float*)p;
    cudaGetSymbolAddress(&p, w_out);  float* oW   = (float*)p;

    const int BIG = 1 << 30;
    const dim3 gGates((BSZ * HID / 4) / 256);

    // [0][1] fp32->tf32 conversions in two launches
    {
        const int n0 = BSZ * 2 * 1024, n1 = 2048 * 1024;
        const int n2 = G3H * OUTD,     n3 = OUTD * HID;
        int tA = n0 + n1 + n2 + n3;
        conv4<<<(tA + 255) / 256, 256>>>(
            x, xr, n0, (const float*)d_in[1], eW, n1,
            (const float*)d_in[3], i0, n2, (const float*)d_in[11], oW, n3);

        const int m0 = G3H * HID;
        int tB = 3 * m0;
        conv4<<<(tB + 255) / 256, 256>>>(
            (const float*)d_in[4], r0, m0, (const float*)d_in[7], i1, m0,
            (const float*)d_in[8], r1, m0, (const float*)d_in[8], r1, 0);
    }

    // [2] Embedding: M=1024 (b*2+l), N=2048, K=1024 -> relu -> h0/h1 + rounded
    gemm_tf32<2><<<dim3(2048 / 128, 1024 / 128), 256, SMEM_BYTES>>>(
        xr, 1024, eW, 1024, 1024,
        xr, 1024, eW, 1024, 1024,
        BIG, nullptr, 0, embB);

    // [3..] 2 warmup steps (zero input: gx0 skipped, gates use bias only)
    for (int w = 0; w < 2; w++) {
        gemm_tf32<0><<<dim3(G3H / 128, BSZ / 128), 256, SMEM_BYTES>>>(   // gh0
            h0r, HID, r0, HID, HID,
            h0r, HID, r0, HID, HID,
            BIG, g + G3H, GLD, nullptr);
        gru_gates<<<gGates, 256>>>(g, bih0, bhh0, h0, h0r, 0);

        // launch index 5 on w==0: the main-loop-sized GEMM (for ncu -s 5 -c 1)
        gemm_tf32<0><<<dim3(GLD / 128, BSZ / 128), 256, SMEM_BYTES>>>(   // gx1|gh1
            h0r, HID, i1, HID, HID,
            h1r, HID, r1, HID, HID,
            G3H, g, GLD, nullptr);
        gru_gates<<<gGates, 256>>>(g, bih1, bhh1, h1, h1r, 1);
    }

    // out0 (split-K) -> preds[:,0,:] + rounded feedback
    gemm_tf32<3><<<dim3(OUTD / 128, BSZ / 128, KSPLIT), 256, SMEM_BYTES>>>(
        h1r, HID, oW, HID, HID / KSPLIT,
        h1r, HID, oW, HID, HID / KSPLIT,
        BIG, part, OUTD, nullptr);
    out_reduce<<<(BSZ * OUTD / 4) / 256, 256>>>(outB, out);

    // Feedback steps t = 1..31
    for (int t = 1; t < 32; t++) {
        gemm_tf32<0><<<dim3(GLD / 128, BSZ / 128), 256, SMEM_BYTES>>>(   // gx0|gh0
            outr, OUTD, i0, OUTD, OUTD,
            h0r,  HID,  r0, HID,  HID,
            G3H, g, GLD, nullptr);
        gru_gates<<<gGates, 256>>>(g, bih0, bhh0, h0, h0r, 1);

        gemm_tf32<0><<<dim3(GLD / 128, BSZ / 128), 256, SMEM_BYTES>>>(   // gx1|gh1
            h0r, HID, i1, HID, HID,
            h1r, HID, r1, HID, HID,
            G3H, g, GLD, nullptr);
        gru_gates<<<gGates, 256>>>(g, bih1, bhh1, h1, h1r, 1);

        gemm_tf32<3><<<dim3(OUTD / 128, BSZ / 128, KSPLIT), 256, SMEM_BYTES>>>(
            h1r, HID, oW, HID, HID / KSPLIT,
            h1r, HID, oW, HID, HID / KSPLIT,
            BIG, part, OUTD, nullptr);
        out_reduce<<<(BSZ * OUTD / 4) / 256, 256>>>(outB, out + (size_t)t * OUTD);
    }
}